// round 13
// baseline (speedup 1.0000x reference)
#include <cuda_runtime.h>
#include <math.h>

#define H      128
#define EVT    4096
#define NN     20000
#define NE     320000
#define MAXN   100000
#define MAXE   300000
#define MSG    640
#define DSTBIT (1 << 30)

// ------------------- device scratch (static, allowed) -------------------
__device__ float    g_aggS[MAXN * MSG];
__device__ float    g_aggD[MAXN * MSG];
__device__ float    g_cntS[MAXN];
__device__ float    g_cntD[MAXN];
__device__ float    g_X   [2 * EVT * MSG];
__device__ float    g_Hst [2 * EVT * H];
__device__ float    g_GI  [2 * EVT * 384];
__device__ float    g_GH  [2 * EVT * 384];
__device__ float    g_newMem[2 * EVT * H];
__device__ int      g_tag [MAXN];        // 0-init; monotone atomicMax keys
// unique-edge machinery
__device__ int      g_flag[MAXE];        // 0-init; cleared at end of each launch
__device__ int      g_list[MAXE];
__device__ int      g_slot[MAXE];
__device__ int      g_ucount;            // 0-init; reset at end of each launch
__device__ float    g_urelt[MAXE];
__device__ float    g_Ec  [MAXE * H];
__device__ float    g_qkvs[NN * 512];    // [q | k | v | skip]
// dst-sorted edge machinery
__device__ int      g_cnt [NN];
__device__ int      g_off [NN + 1];
__device__ int      g_cur [NN];
__device__ int      g_ss  [NE];          // src, sorted by dst
__device__ int      g_su  [NE];          // unique-eid slot, sorted by dst
// weights
__device__ float    g_wihT[640 * 384];
__device__ float    g_whhT[128 * 384];
__device__ float    g_weT [256 * 128];
__device__ float    g_wcT [128 * 512];
__device__ float    g_bc  [512];

// ------------------- helpers -------------------
__device__ __forceinline__ float get_time(const void* p) {
    int iv = *(const int*)p;
    if (iv > -1000000 && iv < 1000000) return (float)iv;
    return *(const float*)p;
}
__device__ __forceinline__ unsigned f2tf32(float f) {
    unsigned r;
    asm("cvt.rna.tf32.f32 %0, %1;" : "=r"(r) : "f"(f));
    return r;
}
__device__ __forceinline__ void mma_tf32(float* d, const unsigned* a, const unsigned* b) {
    asm("mma.sync.aligned.m16n8k8.row.col.f32.tf32.tf32.f32 "
        "{%0,%1,%2,%3}, {%4,%5,%6,%7}, {%8,%9}, {%0,%1,%2,%3};"
        : "+f"(d[0]), "+f"(d[1]), "+f"(d[2]), "+f"(d[3])
        : "r"(a[0]), "r"(a[1]), "r"(a[2]), "r"(a[3]), "r"(b[0]), "r"(b[1]));
}

// ------------------- K1: fused prep (all independent) -------------------
__global__ void __launch_bounds__(256) k_prep(
    const float* __restrict__ gru_w_ih, const float* __restrict__ gru_w_hh,
    const float* __restrict__ we,
    const float* __restrict__ wq, const float* __restrict__ wk,
    const float* __restrict__ wv, const float* __restrict__ ws,
    const float* __restrict__ bq, const float* __restrict__ bk,
    const float* __restrict__ bv, const float* __restrict__ bs,
    const int* __restrict__ eids,
    const int* __restrict__ sids, const int* __restrict__ dids)
{
    int b = blockIdx.x, tid = threadIdx.x;
    if (b < 960) {
        int o = b * 256 + tid;
        int k = o / 384, n = o % 384;
        g_wihT[o] = gru_w_ih[n * 640 + k];
    } else if (b < 1152) {
        int o = (b - 960) * 256 + tid;
        int k = o / 384, n = o % 384;
        g_whhT[o] = gru_w_hh[n * 128 + k];
    } else if (b < 1280) {
        int o = (b - 1152) * 256 + tid;
        int k = o / 128, n = o % 128;
        g_weT[o] = we[n * 256 + k];
    } else if (b < 1536) {
        int o = (b - 1280) * 256 + tid;
        int k = o >> 9, n = o & 511;
        int grp = n >> 7, r = n & 127;
        const float* w = (grp == 0) ? wq : (grp == 1) ? wk : (grp == 2) ? wv : ws;
        g_wcT[o] = w[r * 128 + k];
        if (k == 0) {
            const float* bb = (grp == 0) ? bq : (grp == 1) ? bk : (grp == 2) ? bv : bs;
            g_bc[n] = bb[r];
        }
    } else if (b < 2786) {
        int j = (b - 1536) * 256 + tid;
        if (j < NE) {
            int e = eids[j];
            if (atomicExch(&g_flag[e], 1) == 0) {
                int u = atomicAdd(&g_ucount, 1);
                g_list[u] = e;
                g_slot[e] = u;
            }
        }
    } else if (b < 2865) {
        int i = (b - 2786) * 256 + tid;
        if (i < NN) g_cnt[i] = 0;
    } else {
        int i = b - 2865;
        int sid = sids[i], did = dids[i];
        for (int t = tid; t < MSG; t += 256) {
            g_aggS[sid * MSG + t] = 0.f;
            g_aggD[did * MSG + t] = 0.f;
        }
        if (tid == 0) { g_cntS[sid] = 0.f; g_cntD[did] = 0.f; }
    }
}

// ------------------- K2: msg + hist + urelt -------------------
__global__ void __launch_bounds__(256) k_phase2(
    const int* __restrict__ et, const int* __restrict__ sids,
    const float* __restrict__ smask, const int* __restrict__ dids,
    const float* __restrict__ dmask, const int* __restrict__ eids,
    const float* __restrict__ eemb, const float* __restrict__ emask,
    const float* __restrict__ ts, const float* __restrict__ last_update,
    const float* __restrict__ memory, const float* __restrict__ time_w,
    const float* __restrict__ time_b, const int* __restrict__ ei,
    const void* __restrict__ timep)
{
    int b = blockIdx.x, tid = threadIdx.x;
    if (b < 2048) {
        int i = b * 2 + (tid >> 7);
        int h = tid & 127;
        float em = emask[i], sm = smask[i], dm = dmask[i];
        int   etv = et[i];
        float tsv = ts[i];
        float el  = last_update[eids[i]];
        float rel = tsv - el * dm;
        float isn = (etv == 3 || etv == 4) ? 1.f : 0.f;
        float targ = tsv * isn + rel * dm;
        float cosv = cosf(targ * time_w[h] + time_b[h]) * em;
        int sid = sids[i], did = dids[i];
        float sv = memory[sid * H + h] * sm;
        float dv = memory[did * H + h] * dm;
        float ev = eemb[i * H + h];
        float typ = (float)etv;
        float* aS = g_aggS + sid * MSG;
        atomicAdd(aS + 0 * H + h, typ  * em);
        atomicAdd(aS + 1 * H + h, sv   * em);
        atomicAdd(aS + 2 * H + h, dv   * em);
        atomicAdd(aS + 3 * H + h, cosv * em);
        atomicAdd(aS + 4 * H + h, ev   * em);
        float* aD = g_aggD + did * MSG;
        atomicAdd(aD + 0 * H + h, typ  * dm);
        atomicAdd(aD + 1 * H + h, dv   * dm);
        atomicAdd(aD + 2 * H + h, sv   * dm);
        atomicAdd(aD + 3 * H + h, cosv * dm);
        atomicAdd(aD + 4 * H + h, ev   * dm);
        if (h == 0) { atomicAdd(&g_cntS[sid], 1.f); atomicAdd(&g_cntD[did], 1.f); }
    } else if (b < 4548) {
        int j = (b - 2048) * 256 + tid;
        if (j < NE) atomicAdd(&g_cnt[ei[NE + j]], 1);
    } else {
        int u = (b - 4548) * 256 + tid;
        if (u < g_ucount)
            g_urelt[u] = get_time(timep) - last_update[g_list[u]];
    }
}

// ------------------- K3: build_xh + scan -------------------
__global__ void __launch_bounds__(512) k_phase3(
    const int* __restrict__ sids, const int* __restrict__ dids,
    const float* __restrict__ memory)
{
    int b = blockIdx.x, t = threadIdx.x;
    if (b < 2 * EVT) {
        bool isS = b < EVT;
        int i = isS ? b : b - EVT;
        int id = isS ? sids[i] : dids[i];
        const float* agg = isS ? g_aggS : g_aggD;
        const float* cnt = isS ? g_cntS : g_cntD;
        float inv = 1.f / fmaxf(cnt[id], 1.f);
        for (int c = t; c < MSG; c += 512)
            g_X[b * MSG + c] = agg[id * MSG + c] * inv;
        if (t < H)
            g_Hst[b * H + t] = memory[id * H + t];
    } else {
        __shared__ int ssum[512];
        const int CH = 40;
        int base = t * CH;
        int loc = 0;
#pragma unroll 4
        for (int i = 0; i < CH; i++) {
            int idx = base + i;
            if (idx < NN) loc += g_cnt[idx];
        }
        ssum[t] = loc;
        __syncthreads();
        for (int off = 1; off < 512; off <<= 1) {
            int v = (t >= off) ? ssum[t - off] : 0;
            __syncthreads();
            ssum[t] += v;
            __syncthreads();
        }
        int run = ssum[t] - loc;
        for (int i = 0; i < CH; i++) {
            int idx = base + i;
            if (idx < NN) {
                g_off[idx] = run;
                g_cur[idx] = run;
                run += g_cnt[idx];
            }
        }
        if (t == 511) g_off[NN] = ssum[511];
    }
}

// ------------------- K4: both GRU GEMMs in one launch (z selects) -------------------
__global__ void __launch_bounds__(256, 2) k_gru_gemms(
    const float* __restrict__ b_ih, const float* __restrict__ b_hh)
{
    int z = blockIdx.z;
    const float* A    = z ? g_Hst  : g_X;
    const float* WT   = z ? g_whhT : g_wihT;
    const float* bias = z ? b_hh   : b_ih;
    float*       C    = z ? g_GH   : g_GI;
    int K = z ? 128 : 640;
    const int N = 384;

    int row0 = blockIdx.x * 128;
    int col0 = blockIdx.y * 128;
    __shared__ unsigned sA[128 * 36];
    __shared__ unsigned sW[32 * 136];
    int tid = threadIdx.x, lane = tid & 31, wid = tid >> 5;
    int wm = wid & 3, wn = wid >> 2;
    int gid = lane >> 2, tig = lane & 3;

    float acc[2][8][4];
#pragma unroll
    for (int mt = 0; mt < 2; mt++)
#pragma unroll
        for (int nt = 0; nt < 8; nt++)
#pragma unroll
            for (int c = 0; c < 4; c++) acc[mt][nt][c] = 0.f;

    for (int kc = 0; kc < K; kc += 32) {
#pragma unroll
        for (int l = 0; l < 4; l++) {
            int idx = tid + l * 256;
            int row = idx >> 3, c4 = (idx & 7) * 4;
            float4 v = *(const float4*)&A[(size_t)(row0 + row) * K + kc + c4];
            uint4 t;
            t.x = f2tf32(v.x); t.y = f2tf32(v.y);
            t.z = f2tf32(v.z); t.w = f2tf32(v.w);
            *(uint4*)&sA[row * 36 + c4] = t;
        }
#pragma unroll
        for (int l = 0; l < 4; l++) {
            int idx = tid + l * 256;
            int k = idx >> 5, n4 = (idx & 31) * 4;
            float4 v = *(const float4*)&WT[(size_t)(kc + k) * N + col0 + n4];
            uint4 t;
            t.x = f2tf32(v.x); t.y = f2tf32(v.y);
            t.z = f2tf32(v.z); t.w = f2tf32(v.w);
            *(uint4*)&sW[k * 136 + n4] = t;
        }
        __syncthreads();
#pragma unroll
        for (int k8 = 0; k8 < 32; k8 += 8) {
            unsigned a[2][4];
#pragma unroll
            for (int mt = 0; mt < 2; mt++) {
                int r = wm * 32 + mt * 16;
                a[mt][0] = sA[(r + gid    ) * 36 + k8 + tig    ];
                a[mt][1] = sA[(r + gid + 8) * 36 + k8 + tig    ];
                a[mt][2] = sA[(r + gid    ) * 36 + k8 + tig + 4];
                a[mt][3] = sA[(r + gid + 8) * 36 + k8 + tig + 4];
            }
#pragma unroll
            for (int nt = 0; nt < 8; nt++) {
                int n = wn * 64 + nt * 8 + gid;
                unsigned b[2];
                b[0] = sW[(k8 + tig    ) * 136 + n];
                b[1] = sW[(k8 + tig + 4) * 136 + n];
                mma_tf32(acc[0][nt], a[0], b);
                mma_tf32(acc[1][nt], a[1], b);
            }
        }
        __syncthreads();
    }
#pragma unroll
    for (int mt = 0; mt < 2; mt++) {
#pragma unroll
        for (int nt = 0; nt < 8; nt++) {
            int col = col0 + wn * 64 + nt * 8 + tig * 2;
            float b0 = bias[col], b1 = bias[col + 1];
            int r0 = row0 + wm * 32 + mt * 16 + gid;
            float2 o0 = make_float2(acc[mt][nt][0] + b0, acc[mt][nt][1] + b1);
            float2 o1 = make_float2(acc[mt][nt][2] + b0, acc[mt][nt][3] + b1);
            *(float2*)&C[(size_t)r0 * N + col] = o0;
            *(float2*)&C[(size_t)(r0 + 8) * N + col] = o1;
        }
    }
}

// ------------------- K5: fused E-GEMM (A built on the fly: cos | EF gather) -------------------
__global__ void __launch_bounds__(256, 2) k_egemm(
    const float* __restrict__ EF, const float* __restrict__ tw,
    const float* __restrict__ tb, const float* __restrict__ WT,
    float* __restrict__ C)
{
    int M = g_ucount;
    int row0 = blockIdx.x * 128;
    if (row0 >= M) return;
    __shared__ unsigned sA[128 * 36];
    __shared__ unsigned sW[32 * 136];
    int tid = threadIdx.x, lane = tid & 31, wid = tid >> 5;
    int wm = wid & 3, wn = wid >> 2;
    int gid = lane >> 2, tig = lane & 3;

    float acc[2][8][4];
#pragma unroll
    for (int mt = 0; mt < 2; mt++)
#pragma unroll
        for (int nt = 0; nt < 8; nt++)
#pragma unroll
            for (int c = 0; c < 4; c++) acc[mt][nt][c] = 0.f;

    for (int kc = 0; kc < 256; kc += 32) {
#pragma unroll
        for (int l = 0; l < 4; l++) {
            int idx = tid + l * 256;
            int row = idx >> 3, c4 = (idx & 7) * 4;
            int r = row0 + row;
            float4 v = make_float4(0.f, 0.f, 0.f, 0.f);
            if (r < M) {
                int col = kc + c4;
                if (col < 128) {
                    float relt = g_urelt[r];
                    v.x = __cosf(relt * tw[col    ] + tb[col    ]);
                    v.y = __cosf(relt * tw[col + 1] + tb[col + 1]);
                    v.z = __cosf(relt * tw[col + 2] + tb[col + 2]);
                    v.w = __cosf(relt * tw[col + 3] + tb[col + 3]);
                } else {
                    int e = g_list[r];
                    v = *(const float4*)&EF[(size_t)e * H + col - 128];
                }
            }
            uint4 t;
            t.x = f2tf32(v.x); t.y = f2tf32(v.y);
            t.z = f2tf32(v.z); t.w = f2tf32(v.w);
            *(uint4*)&sA[row * 36 + c4] = t;
        }
#pragma unroll
        for (int l = 0; l < 4; l++) {
            int idx = tid + l * 256;
            int k = idx >> 5, n4 = (idx & 31) * 4;
            float4 v = *(const float4*)&WT[(size_t)(kc + k) * 128 + n4];
            uint4 t;
            t.x = f2tf32(v.x); t.y = f2tf32(v.y);
            t.z = f2tf32(v.z); t.w = f2tf32(v.w);
            *(uint4*)&sW[k * 136 + n4] = t;
        }
        __syncthreads();
#pragma unroll
        for (int k8 = 0; k8 < 32; k8 += 8) {
            unsigned a[2][4];
#pragma unroll
            for (int mt = 0; mt < 2; mt++) {
                int r = wm * 32 + mt * 16;
                a[mt][0] = sA[(r + gid    ) * 36 + k8 + tig    ];
                a[mt][1] = sA[(r + gid + 8) * 36 + k8 + tig    ];
                a[mt][2] = sA[(r + gid    ) * 36 + k8 + tig + 4];
                a[mt][3] = sA[(r + gid + 8) * 36 + k8 + tig + 4];
            }
#pragma unroll
            for (int nt = 0; nt < 8; nt++) {
                int n = wn * 64 + nt * 8 + gid;
                unsigned b[2];
                b[0] = sW[(k8 + tig    ) * 136 + n];
                b[1] = sW[(k8 + tig + 4) * 136 + n];
                mma_tf32(acc[0][nt], a[0], b);
                mma_tf32(acc[1][nt], a[1], b);
            }
        }
        __syncthreads();
    }
#pragma unroll
    for (int mt = 0; mt < 2; mt++) {
#pragma unroll
        for (int nt = 0; nt < 8; nt++) {
            int col = wn * 64 + nt * 8 + tig * 2;
            int r0 = row0 + wm * 32 + mt * 16 + gid;
            if (r0 < M) {
                float2 o = make_float2(acc[mt][nt][0], acc[mt][nt][1]);
                *(float2*)&C[(size_t)r0 * 128 + col] = o;
            }
            if (r0 + 8 < M) {
                float2 o = make_float2(acc[mt][nt][2], acc[mt][nt][3]);
                *(float2*)&C[(size_t)(r0 + 8) * 128 + col] = o;
            }
        }
    }
}

// ------------------- K6: gru_act + scatter + tag -------------------
__global__ void __launch_bounds__(256) k_phase4(
    const int* __restrict__ ei, const int* __restrict__ eids,
    const int* __restrict__ sids, const int* __restrict__ dids)
{
    int b = blockIdx.x, tid = threadIdx.x;
    if (b < 4096) {
        int idx = b * 256 + tid;
        int r = idx >> 7, h = idx & 127;
        float ir = g_GI[r * 384 + h];
        float iz = g_GI[r * 384 + 128 + h];
        float in_ = g_GI[r * 384 + 256 + h];
        float hr = g_GH[r * 384 + h];
        float hz = g_GH[r * 384 + 128 + h];
        float hn = g_GH[r * 384 + 256 + h];
        float rr = 1.f / (1.f + expf(-(ir + hr)));
        float zz = 1.f / (1.f + expf(-(iz + hz)));
        float nn = tanhf(in_ + rr * hn);
        g_newMem[idx] = (1.f - zz) * nn + zz * g_Hst[idx];
    } else if (b < 5346) {
        int j = (b - 4096) * 256 + tid;
        if (j < NE) {
            int d = ei[NE + j];
            int pos = atomicAdd(&g_cur[d], 1);
            g_ss[pos] = ei[j];
            g_su[pos] = g_slot[eids[j]];
        }
    } else {
        int t = (b - 5346) * 256 + tid;
        if (t < 2 * EVT) {
            bool isD = t >= EVT;
            int i = isD ? t - EVT : t;
            int id = isD ? dids[i] : sids[i];
            int key = (isD ? DSTBIT : 0) | (i + 1);
            atomicMax(&g_tag[id], key);
        }
    }
}

// ------------------- K7: q|k|v|skip GEMM with fused x gather -------------------
__global__ void __launch_bounds__(256, 2) k_qkvs_gemm(
    const int* __restrict__ node_ids, const float* __restrict__ NF,
    const float* __restrict__ memory)
{
    const int M = NN, K = 128, N = 512;
    int row0 = blockIdx.x * 128;
    int col0 = blockIdx.y * 128;
    __shared__ unsigned sA[128 * 36];
    __shared__ unsigned sW[32 * 136];
    int tid = threadIdx.x, lane = tid & 31, wid = tid >> 5;
    int wm = wid & 3, wn = wid >> 2;
    int gid = lane >> 2, tig = lane & 3;

    float acc[2][8][4];
#pragma unroll
    for (int mt = 0; mt < 2; mt++)
#pragma unroll
        for (int nt = 0; nt < 8; nt++)
#pragma unroll
            for (int c = 0; c < 4; c++) acc[mt][nt][c] = 0.f;

    for (int kc = 0; kc < K; kc += 32) {
#pragma unroll
        for (int l = 0; l < 4; l++) {
            int idx = tid + l * 256;
            int row = idx >> 3, c4 = (idx & 7) * 4;
            int r = row0 + row;
            float4 v = make_float4(0.f, 0.f, 0.f, 0.f);
            if (r < M) {
                int nid = node_ids[r];
                int tg = g_tag[nid];
                const float* mp;
                if (tg == 0)          mp = &memory[(size_t)nid * H];
                else if (tg & DSTBIT) mp = &g_newMem[(size_t)(EVT + (tg & ~DSTBIT) - 1) * H];
                else                  mp = &g_newMem[(size_t)(tg - 1) * H];
                float4 nf = *(const float4*)&NF[(size_t)nid * H + kc + c4];
                float4 mv = *(const float4*)&mp[kc + c4];
                v = make_float4(nf.x + mv.x, nf.y + mv.y, nf.z + mv.z, nf.w + mv.w);
            }
            uint4 t;
            t.x = f2tf32(v.x); t.y = f2tf32(v.y);
            t.z = f2tf32(v.z); t.w = f2tf32(v.w);
            *(uint4*)&sA[row * 36 + c4] = t;
        }
#pragma unroll
        for (int l = 0; l < 4; l++) {
            int idx = tid + l * 256;
            int k = idx >> 5, n4 = (idx & 31) * 4;
            float4 v = *(const float4*)&g_wcT[(size_t)(kc + k) * N + col0 + n4];
            uint4 t;
            t.x = f2tf32(v.x); t.y = f2tf32(v.y);
            t.z = f2tf32(v.z); t.w = f2tf32(v.w);
            *(uint4*)&sW[k * 136 + n4] = t;
        }
        __syncthreads();
#pragma unroll
        for (int k8 = 0; k8 < 32; k8 += 8) {
            unsigned a[2][4];
#pragma unroll
            for (int mt = 0; mt < 2; mt++) {
                int r = wm * 32 + mt * 16;
                a[mt][0] = sA[(r + gid    ) * 36 + k8 + tig    ];
                a[mt][1] = sA[(r + gid + 8) * 36 + k8 + tig    ];
                a[mt][2] = sA[(r + gid    ) * 36 + k8 + tig + 4];
                a[mt][3] = sA[(r + gid + 8) * 36 + k8 + tig + 4];
            }
#pragma unroll
            for (int nt = 0; nt < 8; nt++) {
                int n = wn * 64 + nt * 8 + gid;
                unsigned b[2];
                b[0] = sW[(k8 + tig    ) * 136 + n];
                b[1] = sW[(k8 + tig + 4) * 136 + n];
                mma_tf32(acc[0][nt], a[0], b);
                mma_tf32(acc[1][nt], a[1], b);
            }
        }
        __syncthreads();
    }
#pragma unroll
    for (int mt = 0; mt < 2; mt++) {
#pragma unroll
        for (int nt = 0; nt < 8; nt++) {
            int col = col0 + wn * 64 + nt * 8 + tig * 2;
            float b0 = g_bc[col], b1 = g_bc[col + 1];
            int r0 = row0 + wm * 32 + mt * 16 + gid;
            if (r0 < M) {
                float2 o = make_float2(acc[mt][nt][0] + b0, acc[mt][nt][1] + b1);
                *(float2*)&g_qkvs[(size_t)r0 * N + col] = o;
            }
            if (r0 + 8 < M) {
                float2 o = make_float2(acc[mt][nt][2] + b0, acc[mt][nt][3] + b1);
                *(float2*)&g_qkvs[(size_t)(r0 + 8) * N + col] = o;
            }
        }
    }
}

// ------------------- K8: attention (8 lanes/edge, 4 groups/warp) + unflag -------------------
// In-loop shfl uses the 8-lane GROUP mask (groups have divergent trip counts;
// full-mask shfl there is UB — that was the Round-12 bug).
__global__ void __launch_bounds__(256) k_attn(float* __restrict__ out,
                                              const int* __restrict__ eids) {
    int b = blockIdx.x;
    if (b >= 2500) {
        int j = (b - 2500) * 256 + threadIdx.x;
        if (j < NE) g_flag[eids[j]] = 0;
        if (j == 0) g_ucount = 0;
        return;
    }
    int warp = threadIdx.x >> 5, lane = threadIdx.x & 31;
    int d = b * 8 + warp;
    if (d >= NN) return;
    int grp = lane >> 3, l8 = lane & 7;          // 4 groups of 8 lanes
    unsigned gmask = 0xFFu << (grp * 8);         // lanes of THIS group only
    int off0 = g_off[d], off1 = g_off[d + 1];

    // lane covers channels [l8*16, l8*16+16)
    float4 q0 = *(const float4*)&g_qkvs[(size_t)d * 512 + l8 * 16     ];
    float4 q1 = *(const float4*)&g_qkvs[(size_t)d * 512 + l8 * 16 + 4 ];
    float4 q2 = *(const float4*)&g_qkvs[(size_t)d * 512 + l8 * 16 + 8 ];
    float4 q3 = *(const float4*)&g_qkvs[(size_t)d * 512 + l8 * 16 + 12];

    float m = -1e30f, den = 0.f;
    float acc[16];
#pragma unroll
    for (int c = 0; c < 16; c++) acc[c] = 0.f;

    for (int i = off0 + grp; i < off1; i += 4) {
        int s = g_ss[i], u = g_su[i];
        const float* kp = &g_qkvs[(size_t)s * 512 + 128 + l8 * 16];
        const float* ep = &g_Ec  [(size_t)u * H         + l8 * 16];
        const float* vp = &g_qkvs[(size_t)s * 512 + 256 + l8 * 16];
        float4 k0 = *(const float4*)(kp    ), k1 = *(const float4*)(kp + 4);
        float4 k2 = *(const float4*)(kp + 8), k3 = *(const float4*)(kp + 12);
        float4 e0 = *(const float4*)(ep    ), e1 = *(const float4*)(ep + 4);
        float4 e2 = *(const float4*)(ep + 8), e3 = *(const float4*)(ep + 12);
        float4 v0 = *(const float4*)(vp    ), v1 = *(const float4*)(vp + 4);
        float4 v2 = *(const float4*)(vp + 8), v3 = *(const float4*)(vp + 12);

        float ke[16];
        ke[0]=k0.x+e0.x; ke[1]=k0.y+e0.y; ke[2]=k0.z+e0.z; ke[3]=k0.w+e0.w;
        ke[4]=k1.x+e1.x; ke[5]=k1.y+e1.y; ke[6]=k1.z+e1.z; ke[7]=k1.w+e1.w;
        ke[8]=k2.x+e2.x; ke[9]=k2.y+e2.y; ke[10]=k2.z+e2.z; ke[11]=k2.w+e2.w;
        ke[12]=k3.x+e3.x; ke[13]=k3.y+e3.y; ke[14]=k3.z+e3.z; ke[15]=k3.w+e3.w;

        float p = q0.x*ke[0] + q0.y*ke[1] + q0.z*ke[2] + q0.w*ke[3]
                + q1.x*ke[4] + q1.y*ke[5] + q1.z*ke[6] + q1.w*ke[7]
                + q2.x*ke[8] + q2.y*ke[9] + q2.z*ke[10] + q2.w*ke[11]
                + q3.x*ke[12] + q3.y*ke[13] + q3.z*ke[14] + q3.w*ke[15];
#pragma unroll
        for (int o = 4; o; o >>= 1) p += __shfl_xor_sync(gmask, p, o);
        float a = p * 0.08838834764831845f;      // 1/sqrt(128)
        float mn = fmaxf(m, a);
        float scale = __expf(m - mn);
        float w = __expf(a - mn);
        den = den * scale + w;
        float ve[16];
        ve[0]=v0.x+e0.x; ve[1]=v0.y+e0.y; ve[2]=v0.z+e0.z; ve[3]=v0.w+e0.w;
        ve[4]=v1.x+e1.x; ve[5]=v1.y+e1.y; ve[6]=v1.z+e1.z; ve[7]=v1.w+e1.w;
        ve[8]=v2.x+e2.x; ve[9]=v2.y+e2.y; ve[10]=v2.z+e2.z; ve[11]=v2.w+e2.w;
        ve[12]=v3.x+e3.x; ve[13]=v3.y+e3.y; ve[14]=v3.z+e3.z; ve[15]=v3.w+e3.w;
#pragma unroll
        for (int c = 0; c < 16; c++) acc[c] = acc[c] * scale + w * ve[c];
        m = mn;
    }

    // merge the 4 group-states (warp fully reconverged here; full mask OK)
#pragma unroll
    for (int o = 8; o <= 16; o <<= 1) {
        float mo   = __shfl_xor_sync(0xffffffffu, m, o);
        float deno = __shfl_xor_sync(0xffffffffu, den, o);
        float mn = fmaxf(m, mo);
        float s1 = __expf(m - mn), s2 = __expf(mo - mn);
        den = den * s1 + deno * s2;
#pragma unroll
        for (int c = 0; c < 16; c++) {
            float ao = __shfl_xor_sync(0xffffffffu, acc[c], o);
            acc[c] = acc[c] * s1 + ao * s2;
        }
        m = mn;
    }

    if (grp == 0) {
        float rden = 1.f / fmaxf(den, 1e-16f);
        const float* sp = &g_qkvs[(size_t)d * 512 + 384 + l8 * 16];
        float* op = &out[(size_t)d * H + l8 * 16];
#pragma unroll
        for (int c4 = 0; c4 < 4; c4++) {
            float4 sk = *(const float4*)(sp + c4 * 4);
            float4 o4 = make_float4(sk.x + acc[c4 * 4 + 0] * rden,
                                    sk.y + acc[c4 * 4 + 1] * rden,
                                    sk.z + acc[c4 * 4 + 2] * rden,
                                    sk.w + acc[c4 * 4 + 3] * rden);
            *(float4*)(op + c4 * 4) = o4;
        }
    }
}

// ------------------- host -------------------
static float* symf(const void* s) {
    void* p = nullptr;
    cudaGetSymbolAddress(&p, s);
    return (float*)p;
}

extern "C" void kernel_launch(void* const* d_in, const int* in_sizes, int n_in,
                              void* d_out, int out_size)
{
    const int*   event_type_ids = (const int*)  d_in[0];
    const int*   src_ids        = (const int*)  d_in[1];
    const float* src_mask       = (const float*)d_in[2];
    const int*   dst_ids        = (const int*)  d_in[3];
    const float* dst_mask       = (const float*)d_in[4];
    const int*   event_edge_ids = (const int*)  d_in[5];
    const float* event_emb      = (const float*)d_in[6];
    const float* event_mask     = (const float*)d_in[7];
    const float* event_ts       = (const float*)d_in[8];
    const int*   node_ids       = (const int*)  d_in[9];
    const int*   edge_ids       = (const int*)  d_in[10];
    const int*   edge_index     = (const int*)  d_in[11];
    const void*  timep          =               d_in[12];
    const float* memory         = (const float*)d_in[13];
    const float* last_update    = (const float*)d_in[14];
    const float* node_features  = (const float*)d_in[15];
    const float* edge_features  = (const float*)d_in[16];
    const float* time_w         = (const float*)d_in[17];
    const float* time_b         = (const float*)d_in[18];
    const float* gru_w_ih       = (const float*)d_in[19];
    const float* gru_w_hh       = (const float*)d_in[20];
    const float* gru_b_ih       = (const float*)d_in[21];
    const float* gru_b_hh       = (const float*)d_in[22];
    const float* wq             = (const float*)d_in[23];
    const float* bq             = (const float*)d_in[24];
    const float* wk             = (const float*)d_in[25];
    const float* bk             = (const float*)d_in[26];
    const float* wv             = (const float*)d_in[27];
    const float* bv             = (const float*)d_in[28];
    const float* we             = (const float*)d_in[29];
    const float* wskip          = (const float*)d_in[30];
    const float* bskip          = (const float*)d_in[31];
    float* out = (float*)d_out;

    float* pEc  = symf(g_Ec);
    float* pweT = symf(g_weT);

    // K1: prep (transposes, packw, flag, cnt0, zero)
    k_prep<<<6961, 256>>>(gru_w_ih, gru_w_hh, we, wq, wk, wv, wskip,
                          bq, bk, bv, bskip, edge_ids, src_ids, dst_ids);
    // K2: msg + hist + urelt
    k_phase2<<<6892, 256>>>(event_type_ids, src_ids, src_mask, dst_ids, dst_mask,
                            event_edge_ids, event_emb, event_mask, event_ts,
                            last_update, memory, time_w, time_b, edge_index, timep);
    // K3: build_xh + scan
    k_phase3<<<2 * EVT + 1, 512>>>(src_ids, dst_ids, memory);
    // K4: GRU GEMMs (both in one launch)
    k_gru_gemms<<<dim3(64, 3, 2), 256>>>(gru_b_ih, gru_b_hh);
    // K5: fused E-GEMM over unique eids
    k_egemm<<<(MAXE + 127) / 128, 256>>>(edge_features, time_w, time_b, pweT, pEc);
    // K6: gru_act + scatter + tag
    k_phase4<<<5378, 256>>>(edge_index, edge_ids, src_ids, dst_ids);
    // K7: q|k|v|skip GEMM with fused x gather
    k_qkvs_gemm<<<dim3((NN + 127) / 128, 4), 256>>>(node_ids, node_features, memory);
    // K8: attention (group-masked shfl) + unflag
    k_attn<<<2500 + (NE + 255) / 256, 256>>>(out, edge_ids);
}

// round 14
// speedup vs baseline: 1.1075x; 1.1075x over previous
#include <cuda_runtime.h>
#include <math.h>

#define H      128
#define EVT    4096
#define NN     20000
#define NE     320000
#define MAXN   100000
#define MAXE   300000
#define MSG    640
#define DSTBIT (1 << 30)

// ------------------- device scratch (static, allowed) -------------------
__device__ float    g_aggS[MAXN * MSG];
__device__ float    g_aggD[MAXN * MSG];
__device__ float    g_cntS[MAXN];
__device__ float    g_cntD[MAXN];
__device__ float    g_Hst [2 * EVT * H];
__device__ float    g_GI  [2 * EVT * 384];
__device__ float    g_GH  [2 * EVT * 384];
__device__ float    g_newMem[2 * EVT * H];
__device__ int      g_tag [MAXN];        // 0-init; monotone atomicMax keys
// unique-edge machinery
__device__ int      g_flag[MAXE];        // 0-init; cleared at end of each launch
__device__ int      g_list[MAXE];
__device__ int      g_slot[MAXE];
__device__ int      g_ucount;            // 0-init; reset at end of each launch
__device__ float    g_urelt[MAXE];
__device__ float    g_Ec  [MAXE * H];
__device__ float    g_qkvs[NN * 512];    // [q | k | v | skip]
// dst-sorted edge machinery
__device__ int      g_cnt [NN];
__device__ int      g_off [NN + 1];
__device__ int      g_cur [NN];
__device__ int      g_ss  [NE];          // src, sorted by dst
__device__ int      g_su  [NE];          // unique-eid slot, sorted by dst
// weights
__device__ float    g_wihT[640 * 384];
__device__ float    g_whhT[128 * 384];
__device__ float    g_weT [256 * 128];
__device__ float    g_wcT [128 * 512];
__device__ float    g_bc  [512];

// ------------------- helpers -------------------
__device__ __forceinline__ float get_time(const void* p) {
    int iv = *(const int*)p;
    if (iv > -1000000 && iv < 1000000) return (float)iv;
    return *(const float*)p;
}
__device__ __forceinline__ unsigned f2tf32(float f) {
    unsigned r;
    asm("cvt.rna.tf32.f32 %0, %1;" : "=r"(r) : "f"(f));
    return r;
}
__device__ __forceinline__ void mma_tf32(float* d, const unsigned* a, const unsigned* b) {
    asm("mma.sync.aligned.m16n8k8.row.col.f32.tf32.tf32.f32 "
        "{%0,%1,%2,%3}, {%4,%5,%6,%7}, {%8,%9}, {%0,%1,%2,%3};"
        : "+f"(d[0]), "+f"(d[1]), "+f"(d[2]), "+f"(d[3])
        : "r"(a[0]), "r"(a[1]), "r"(a[2]), "r"(a[3]), "r"(b[0]), "r"(b[1]));
}

// ------------------- K1: fused prep (all independent) -------------------
// [0,960) wihT | [960,1152) whhT | [1152,1280) weT | [1280,1536) packw
// [1536,2786) flag | [2786,2865) cnt0 | [2865,6961) zero | [6961,11057) Hst
__global__ void __launch_bounds__(256) k_prep(
    const float* __restrict__ gru_w_ih, const float* __restrict__ gru_w_hh,
    const float* __restrict__ we,
    const float* __restrict__ wq, const float* __restrict__ wk,
    const float* __restrict__ wv, const float* __restrict__ ws,
    const float* __restrict__ bq, const float* __restrict__ bk,
    const float* __restrict__ bv, const float* __restrict__ bs,
    const int* __restrict__ eids,
    const int* __restrict__ sids, const int* __restrict__ dids,
    const float* __restrict__ memory)
{
    int b = blockIdx.x, tid = threadIdx.x;
    if (b < 960) {
        int o = b * 256 + tid;
        int k = o / 384, n = o % 384;
        g_wihT[o] = gru_w_ih[n * 640 + k];
    } else if (b < 1152) {
        int o = (b - 960) * 256 + tid;
        int k = o / 384, n = o % 384;
        g_whhT[o] = gru_w_hh[n * 128 + k];
    } else if (b < 1280) {
        int o = (b - 1152) * 256 + tid;
        int k = o / 128, n = o % 128;
        g_weT[o] = we[n * 256 + k];
    } else if (b < 1536) {
        int o = (b - 1280) * 256 + tid;
        int k = o >> 9, n = o & 511;
        int grp = n >> 7, r = n & 127;
        const float* w = (grp == 0) ? wq : (grp == 1) ? wk : (grp == 2) ? wv : ws;
        g_wcT[o] = w[r * 128 + k];
        if (k == 0) {
            const float* bb = (grp == 0) ? bq : (grp == 1) ? bk : (grp == 2) ? bv : bs;
            g_bc[n] = bb[r];
        }
    } else if (b < 2786) {
        int j = (b - 1536) * 256 + tid;
        if (j < NE) {
            int e = eids[j];
            if (atomicExch(&g_flag[e], 1) == 0) {
                int u = atomicAdd(&g_ucount, 1);
                g_list[u] = e;
                g_slot[e] = u;
            }
        }
    } else if (b < 2865) {
        int i = (b - 2786) * 256 + tid;
        if (i < NN) g_cnt[i] = 0;
    } else if (b < 6961) {
        int i = b - 2865;
        int sid = sids[i], did = dids[i];
        for (int t = tid; t < MSG; t += 256) {
            g_aggS[sid * MSG + t] = 0.f;
            g_aggD[did * MSG + t] = 0.f;
        }
        if (tid == 0) { g_cntS[sid] = 0.f; g_cntD[did] = 0.f; }
    } else {
        int rr = (b - 6961) * 2 + (tid >> 7);   // row in [0, 2*EVT)
        int h = tid & 127;
        bool isS = rr < EVT;
        int i = isS ? rr : rr - EVT;
        int id = isS ? sids[i] : dids[i];
        g_Hst[rr * H + h] = memory[id * H + h];
    }
}

// ------------------- K2: msg + hist + urelt -------------------
__global__ void __launch_bounds__(256) k_phase2(
    const int* __restrict__ et, const int* __restrict__ sids,
    const float* __restrict__ smask, const int* __restrict__ dids,
    const float* __restrict__ dmask, const int* __restrict__ eids,
    const float* __restrict__ eemb, const float* __restrict__ emask,
    const float* __restrict__ ts, const float* __restrict__ last_update,
    const float* __restrict__ memory, const float* __restrict__ time_w,
    const float* __restrict__ time_b, const int* __restrict__ ei,
    const void* __restrict__ timep)
{
    int b = blockIdx.x, tid = threadIdx.x;
    if (b < 2048) {
        int i = b * 2 + (tid >> 7);
        int h = tid & 127;
        float em = emask[i], sm = smask[i], dm = dmask[i];
        int   etv = et[i];
        float tsv = ts[i];
        float el  = last_update[eids[i]];
        float rel = tsv - el * dm;
        float isn = (etv == 3 || etv == 4) ? 1.f : 0.f;
        float targ = tsv * isn + rel * dm;
        float cosv = cosf(targ * time_w[h] + time_b[h]) * em;
        int sid = sids[i], did = dids[i];
        float sv = memory[sid * H + h] * sm;
        float dv = memory[did * H + h] * dm;
        float ev = eemb[i * H + h];
        float typ = (float)etv;
        float* aS = g_aggS + sid * MSG;
        atomicAdd(aS + 0 * H + h, typ  * em);
        atomicAdd(aS + 1 * H + h, sv   * em);
        atomicAdd(aS + 2 * H + h, dv   * em);
        atomicAdd(aS + 3 * H + h, cosv * em);
        atomicAdd(aS + 4 * H + h, ev   * em);
        float* aD = g_aggD + did * MSG;
        atomicAdd(aD + 0 * H + h, typ  * dm);
        atomicAdd(aD + 1 * H + h, dv   * dm);
        atomicAdd(aD + 2 * H + h, sv   * dm);
        atomicAdd(aD + 3 * H + h, cosv * dm);
        atomicAdd(aD + 4 * H + h, ev   * dm);
        if (h == 0) { atomicAdd(&g_cntS[sid], 1.f); atomicAdd(&g_cntD[did], 1.f); }
    } else if (b < 4548) {
        int j = (b - 2048) * 256 + tid;
        if (j < NE) atomicAdd(&g_cnt[ei[NE + j]], 1);
    } else {
        int u = (b - 4548) * 256 + tid;
        if (u < g_ucount)
            g_urelt[u] = get_time(timep) - last_update[g_list[u]];
    }
}

// ------------------- K3: single-block scan of g_cnt -> g_off / g_cur -------------------
__global__ void __launch_bounds__(512) k_scan() {
    __shared__ int ssum[512];
    int t = threadIdx.x;
    const int CH = 40;
    int base = t * CH;
    int loc = 0;
#pragma unroll 4
    for (int i = 0; i < CH; i++) {
        int idx = base + i;
        if (idx < NN) loc += g_cnt[idx];
    }
    ssum[t] = loc;
    __syncthreads();
    for (int off = 1; off < 512; off <<= 1) {
        int v = (t >= off) ? ssum[t - off] : 0;
        __syncthreads();
        ssum[t] += v;
        __syncthreads();
    }
    int run = ssum[t] - loc;
    for (int i = 0; i < CH; i++) {
        int idx = base + i;
        if (idx < NN) {
            g_off[idx] = run;
            g_cur[idx] = run;
            run += g_cnt[idx];
        }
    }
    if (t == 511) g_off[NN] = ssum[511];
}

// ------------------- K4: both GRU GEMMs; z=0 gathers agg directly -------------------
__global__ void __launch_bounds__(256, 2) k_gru_gemms(
    const float* __restrict__ b_ih, const float* __restrict__ b_hh,
    const int* __restrict__ sids, const int* __restrict__ dids)
{
    int z = blockIdx.z;
    const float* WT   = z ? g_whhT : g_wihT;
    const float* bias = z ? b_hh   : b_ih;
    float*       C    = z ? g_GH   : g_GI;
    int K = z ? 128 : 640;
    const int N = 384;

    int row0 = blockIdx.x * 128;
    int col0 = blockIdx.y * 128;
    __shared__ unsigned sA[128 * 36];
    __shared__ unsigned sW[32 * 136];
    int tid = threadIdx.x, lane = tid & 31, wid = tid >> 5;
    int wm = wid & 3, wn = wid >> 2;
    int gid = lane >> 2, tig = lane & 3;

    // hoisted per-thread A-row metadata (z=0 path); isS uniform per block
    const float* aptr[4];
    float ainv[4];
    if (z == 0) {
        bool isS = row0 < EVT;
#pragma unroll
        for (int l = 0; l < 4; l++) {
            int row = (tid + l * 256) >> 3;
            int r = row0 + row;
            int i = isS ? r : r - EVT;
            int id = isS ? sids[i] : dids[i];
            aptr[l] = (isS ? g_aggS : g_aggD) + (size_t)id * MSG;
            ainv[l] = 1.f / fmaxf((isS ? g_cntS : g_cntD)[id], 1.f);
        }
    }

    float acc[2][8][4];
#pragma unroll
    for (int mt = 0; mt < 2; mt++)
#pragma unroll
        for (int nt = 0; nt < 8; nt++)
#pragma unroll
            for (int c = 0; c < 4; c++) acc[mt][nt][c] = 0.f;

    for (int kc = 0; kc < K; kc += 32) {
#pragma unroll
        for (int l = 0; l < 4; l++) {
            int idx = tid + l * 256;
            int row = idx >> 3, c4 = (idx & 7) * 4;
            float4 v;
            if (z == 0) {
                v = *(const float4*)&aptr[l][kc + c4];
                v.x *= ainv[l]; v.y *= ainv[l]; v.z *= ainv[l]; v.w *= ainv[l];
            } else {
                v = *(const float4*)&g_Hst[(size_t)(row0 + row) * H + kc + c4];
            }
            uint4 t;
            t.x = f2tf32(v.x); t.y = f2tf32(v.y);
            t.z = f2tf32(v.z); t.w = f2tf32(v.w);
            *(uint4*)&sA[row * 36 + c4] = t;
        }
#pragma unroll
        for (int l = 0; l < 4; l++) {
            int idx = tid + l * 256;
            int k = idx >> 5, n4 = (idx & 31) * 4;
            float4 v = *(const float4*)&WT[(size_t)(kc + k) * N + col0 + n4];
            uint4 t;
            t.x = f2tf32(v.x); t.y = f2tf32(v.y);
            t.z = f2tf32(v.z); t.w = f2tf32(v.w);
            *(uint4*)&sW[k * 136 + n4] = t;
        }
        __syncthreads();
#pragma unroll
        for (int k8 = 0; k8 < 32; k8 += 8) {
            unsigned a[2][4];
#pragma unroll
            for (int mt = 0; mt < 2; mt++) {
                int r = wm * 32 + mt * 16;
                a[mt][0] = sA[(r + gid    ) * 36 + k8 + tig    ];
                a[mt][1] = sA[(r + gid + 8) * 36 + k8 + tig    ];
                a[mt][2] = sA[(r + gid    ) * 36 + k8 + tig + 4];
                a[mt][3] = sA[(r + gid + 8) * 36 + k8 + tig + 4];
            }
#pragma unroll
            for (int nt = 0; nt < 8; nt++) {
                int n = wn * 64 + nt * 8 + gid;
                unsigned b[2];
                b[0] = sW[(k8 + tig    ) * 136 + n];
                b[1] = sW[(k8 + tig + 4) * 136 + n];
                mma_tf32(acc[0][nt], a[0], b);
                mma_tf32(acc[1][nt], a[1], b);
            }
        }
        __syncthreads();
    }
#pragma unroll
    for (int mt = 0; mt < 2; mt++) {
#pragma unroll
        for (int nt = 0; nt < 8; nt++) {
            int col = col0 + wn * 64 + nt * 8 + tig * 2;
            float b0 = bias[col], b1 = bias[col + 1];
            int r0 = row0 + wm * 32 + mt * 16 + gid;
            float2 o0 = make_float2(acc[mt][nt][0] + b0, acc[mt][nt][1] + b1);
            float2 o1 = make_float2(acc[mt][nt][2] + b0, acc[mt][nt][3] + b1);
            *(float2*)&C[(size_t)r0 * N + col] = o0;
            *(float2*)&C[(size_t)(r0 + 8) * N + col] = o1;
        }
    }
}

// ------------------- K5: fused E-GEMM (A built on the fly: cos | EF gather) -------------------
__global__ void __launch_bounds__(256, 2) k_egemm(
    const float* __restrict__ EF, const float* __restrict__ tw,
    const float* __restrict__ tb, const float* __restrict__ WT,
    float* __restrict__ C)
{
    int M = g_ucount;
    int row0 = blockIdx.x * 128;
    if (row0 >= M) return;
    __shared__ unsigned sA[128 * 36];
    __shared__ unsigned sW[32 * 136];
    int tid = threadIdx.x, lane = tid & 31, wid = tid >> 5;
    int wm = wid & 3, wn = wid >> 2;
    int gid = lane >> 2, tig = lane & 3;

    float acc[2][8][4];
#pragma unroll
    for (int mt = 0; mt < 2; mt++)
#pragma unroll
        for (int nt = 0; nt < 8; nt++)
#pragma unroll
            for (int c = 0; c < 4; c++) acc[mt][nt][c] = 0.f;

    for (int kc = 0; kc < 256; kc += 32) {
#pragma unroll
        for (int l = 0; l < 4; l++) {
            int idx = tid + l * 256;
            int row = idx >> 3, c4 = (idx & 7) * 4;
            int r = row0 + row;
            float4 v = make_float4(0.f, 0.f, 0.f, 0.f);
            if (r < M) {
                int col = kc + c4;
                if (col < 128) {
                    float relt = g_urelt[r];
                    v.x = __cosf(relt * tw[col    ] + tb[col    ]);
                    v.y = __cosf(relt * tw[col + 1] + tb[col + 1]);
                    v.z = __cosf(relt * tw[col + 2] + tb[col + 2]);
                    v.w = __cosf(relt * tw[col + 3] + tb[col + 3]);
                } else {
                    int e = g_list[r];
                    v = *(const float4*)&EF[(size_t)e * H + col - 128];
                }
            }
            uint4 t;
            t.x = f2tf32(v.x); t.y = f2tf32(v.y);
            t.z = f2tf32(v.z); t.w = f2tf32(v.w);
            *(uint4*)&sA[row * 36 + c4] = t;
        }
#pragma unroll
        for (int l = 0; l < 4; l++) {
            int idx = tid + l * 256;
            int k = idx >> 5, n4 = (idx & 31) * 4;
            float4 v = *(const float4*)&WT[(size_t)(kc + k) * 128 + n4];
            uint4 t;
            t.x = f2tf32(v.x); t.y = f2tf32(v.y);
            t.z = f2tf32(v.z); t.w = f2tf32(v.w);
            *(uint4*)&sW[k * 136 + n4] = t;
        }
        __syncthreads();
#pragma unroll
        for (int k8 = 0; k8 < 32; k8 += 8) {
            unsigned a[2][4];
#pragma unroll
            for (int mt = 0; mt < 2; mt++) {
                int r = wm * 32 + mt * 16;
                a[mt][0] = sA[(r + gid    ) * 36 + k8 + tig    ];
                a[mt][1] = sA[(r + gid + 8) * 36 + k8 + tig    ];
                a[mt][2] = sA[(r + gid    ) * 36 + k8 + tig + 4];
                a[mt][3] = sA[(r + gid + 8) * 36 + k8 + tig + 4];
            }
#pragma unroll
            for (int nt = 0; nt < 8; nt++) {
                int n = wn * 64 + nt * 8 + gid;
                unsigned b[2];
                b[0] = sW[(k8 + tig    ) * 136 + n];
                b[1] = sW[(k8 + tig + 4) * 136 + n];
                mma_tf32(acc[0][nt], a[0], b);
                mma_tf32(acc[1][nt], a[1], b);
            }
        }
        __syncthreads();
    }
#pragma unroll
    for (int mt = 0; mt < 2; mt++) {
#pragma unroll
        for (int nt = 0; nt < 8; nt++) {
            int col = wn * 64 + nt * 8 + tig * 2;
            int r0 = row0 + wm * 32 + mt * 16 + gid;
            if (r0 < M) {
                float2 o = make_float2(acc[mt][nt][0], acc[mt][nt][1]);
                *(float2*)&C[(size_t)r0 * 128 + col] = o;
            }
            if (r0 + 8 < M) {
                float2 o = make_float2(acc[mt][nt][2], acc[mt][nt][3]);
                *(float2*)&C[(size_t)(r0 + 8) * 128 + col] = o;
            }
        }
    }
}

// ------------------- K6: gru_act + scatter + tag -------------------
__global__ void __launch_bounds__(256) k_phase4(
    const int* __restrict__ ei, const int* __restrict__ eids,
    const int* __restrict__ sids, const int* __restrict__ dids)
{
    int b = blockIdx.x, tid = threadIdx.x;
    if (b < 4096) {
        int idx = b * 256 + tid;
        int r = idx >> 7, h = idx & 127;
        float ir = g_GI[r * 384 + h];
        float iz = g_GI[r * 384 + 128 + h];
        float in_ = g_GI[r * 384 + 256 + h];
        float hr = g_GH[r * 384 + h];
        float hz = g_GH[r * 384 + 128 + h];
        float hn = g_GH[r * 384 + 256 + h];
        float rr = 1.f / (1.f + expf(-(ir + hr)));
        float zz = 1.f / (1.f + expf(-(iz + hz)));
        float nn = tanhf(in_ + rr * hn);
        g_newMem[idx] = (1.f - zz) * nn + zz * g_Hst[idx];
    } else if (b < 5346) {
        int j = (b - 4096) * 256 + tid;
        if (j < NE) {
            int d = ei[NE + j];
            int pos = atomicAdd(&g_cur[d], 1);
            g_ss[pos] = ei[j];
            g_su[pos] = g_slot[eids[j]];
        }
    } else {
        int t = (b - 5346) * 256 + tid;
        if (t < 2 * EVT) {
            bool isD = t >= EVT;
            int i = isD ? t - EVT : t;
            int id = isD ? dids[i] : sids[i];
            int key = (isD ? DSTBIT : 0) | (i + 1);
            atomicMax(&g_tag[id], key);
        }
    }
}

// ------------------- K7: q|k|v|skip GEMM with fused x gather -------------------
__global__ void __launch_bounds__(256, 2) k_qkvs_gemm(
    const int* __restrict__ node_ids, const float* __restrict__ NF,
    const float* __restrict__ memory)
{
    const int M = NN, K = 128, N = 512;
    int row0 = blockIdx.x * 128;
    int col0 = blockIdx.y * 128;
    __shared__ unsigned sA[128 * 36];
    __shared__ unsigned sW[32 * 136];
    int tid = threadIdx.x, lane = tid & 31, wid = tid >> 5;
    int wm = wid & 3, wn = wid >> 2;
    int gid = lane >> 2, tig = lane & 3;

    float acc[2][8][4];
#pragma unroll
    for (int mt = 0; mt < 2; mt++)
#pragma unroll
        for (int nt = 0; nt < 8; nt++)
#pragma unroll
            for (int c = 0; c < 4; c++) acc[mt][nt][c] = 0.f;

    for (int kc = 0; kc < K; kc += 32) {
#pragma unroll
        for (int l = 0; l < 4; l++) {
            int idx = tid + l * 256;
            int row = idx >> 3, c4 = (idx & 7) * 4;
            int r = row0 + row;
            float4 v = make_float4(0.f, 0.f, 0.f, 0.f);
            if (r < M) {
                int nid = node_ids[r];
                int tg = g_tag[nid];
                const float* mp;
                if (tg == 0)          mp = &memory[(size_t)nid * H];
                else if (tg & DSTBIT) mp = &g_newMem[(size_t)(EVT + (tg & ~DSTBIT) - 1) * H];
                else                  mp = &g_newMem[(size_t)(tg - 1) * H];
                float4 nf = *(const float4*)&NF[(size_t)nid * H + kc + c4];
                float4 mv = *(const float4*)&mp[kc + c4];
                v = make_float4(nf.x + mv.x, nf.y + mv.y, nf.z + mv.z, nf.w + mv.w);
            }
            uint4 t;
            t.x = f2tf32(v.x); t.y = f2tf32(v.y);
            t.z = f2tf32(v.z); t.w = f2tf32(v.w);
            *(uint4*)&sA[row * 36 + c4] = t;
        }
#pragma unroll
        for (int l = 0; l < 4; l++) {
            int idx = tid + l * 256;
            int k = idx >> 5, n4 = (idx & 31) * 4;
            float4 v = *(const float4*)&g_wcT[(size_t)(kc + k) * N + col0 + n4];
            uint4 t;
            t.x = f2tf32(v.x); t.y = f2tf32(v.y);
            t.z = f2tf32(v.z); t.w = f2tf32(v.w);
            *(uint4*)&sW[k * 136 + n4] = t;
        }
        __syncthreads();
#pragma unroll
        for (int k8 = 0; k8 < 32; k8 += 8) {
            unsigned a[2][4];
#pragma unroll
            for (int mt = 0; mt < 2; mt++) {
                int r = wm * 32 + mt * 16;
                a[mt][0] = sA[(r + gid    ) * 36 + k8 + tig    ];
                a[mt][1] = sA[(r + gid + 8) * 36 + k8 + tig    ];
                a[mt][2] = sA[(r + gid    ) * 36 + k8 + tig + 4];
                a[mt][3] = sA[(r + gid + 8) * 36 + k8 + tig + 4];
            }
#pragma unroll
            for (int nt = 0; nt < 8; nt++) {
                int n = wn * 64 + nt * 8 + gid;
                unsigned b[2];
                b[0] = sW[(k8 + tig    ) * 136 + n];
                b[1] = sW[(k8 + tig + 4) * 136 + n];
                mma_tf32(acc[0][nt], a[0], b);
                mma_tf32(acc[1][nt], a[1], b);
            }
        }
        __syncthreads();
    }
#pragma unroll
    for (int mt = 0; mt < 2; mt++) {
#pragma unroll
        for (int nt = 0; nt < 8; nt++) {
            int col = col0 + wn * 64 + nt * 8 + tig * 2;
            float b0 = g_bc[col], b1 = g_bc[col + 1];
            int r0 = row0 + wm * 32 + mt * 16 + gid;
            if (r0 < M) {
                float2 o = make_float2(acc[mt][nt][0] + b0, acc[mt][nt][1] + b1);
                *(float2*)&g_qkvs[(size_t)r0 * N + col] = o;
            }
            if (r0 + 8 < M) {
                float2 o = make_float2(acc[mt][nt][2] + b0, acc[mt][nt][3] + b1);
                *(float2*)&g_qkvs[(size_t)(r0 + 8) * N + col] = o;
            }
        }
    }
}

// ------------------- K8: attention (R11 full-warp online softmax) + unflag -------------------
__global__ void __launch_bounds__(256) k_attn(float* __restrict__ out,
                                              const int* __restrict__ eids) {
    int b = blockIdx.x;
    if (b >= 2500) {
        int j = (b - 2500) * 256 + threadIdx.x;
        if (j < NE) g_flag[eids[j]] = 0;
        if (j == 0) g_ucount = 0;
        return;
    }
    int warp = threadIdx.x >> 5, lane = threadIdx.x & 31;
    int d = b * 8 + warp;
    if (d >= NN) return;
    int off0 = g_off[d], off1 = g_off[d + 1];

    float4 q4 = *(const float4*)&g_qkvs[(size_t)d * 512 + lane * 4];
    float m = -1e30f, den = 0.f;
    float4 acc = make_float4(0.f, 0.f, 0.f, 0.f);

    for (int i = off0; i < off1; i++) {
        int s = g_ss[i], u = g_su[i];
        float4 k4 = *(const float4*)&g_qkvs[(size_t)s * 512 + 128 + lane * 4];
        float4 e4 = *(const float4*)&g_Ec  [(size_t)u * H   +       lane * 4];
        float4 v4 = *(const float4*)&g_qkvs[(size_t)s * 512 + 256 + lane * 4];
        float p = q4.x * (k4.x + e4.x) + q4.y * (k4.y + e4.y)
                + q4.z * (k4.z + e4.z) + q4.w * (k4.w + e4.w);
#pragma unroll
        for (int o = 16; o; o >>= 1) p += __shfl_xor_sync(0xffffffffu, p, o);
        float a = p * 0.08838834764831845f;          // 1/sqrt(128)
        float mn = fmaxf(m, a);
        float scale = __expf(m - mn);
        float w = __expf(a - mn);
        den = den * scale + w;
        acc.x = acc.x * scale + w * (v4.x + e4.x);
        acc.y = acc.y * scale + w * (v4.y + e4.y);
        acc.z = acc.z * scale + w * (v4.z + e4.z);
        acc.w = acc.w * scale + w * (v4.w + e4.w);
        m = mn;
    }
    float rden = 1.f / fmaxf(den, 1e-16f);
    float4 sk = *(const float4*)&g_qkvs[(size_t)d * 512 + 384 + lane * 4];
    float4 o4 = make_float4(sk.x + acc.x * rden, sk.y + acc.y * rden,
                            sk.z + acc.z * rden, sk.w + acc.w * rden);
    *(float4*)&out[(size_t)d * H + lane * 4] = o4;
}

// ------------------- host -------------------
static float* symf(const void* s) {
    void* p = nullptr;
    cudaGetSymbolAddress(&p, s);
    return (float*)p;
}

extern "C" void kernel_launch(void* const* d_in, const int* in_sizes, int n_in,
                              void* d_out, int out_size)
{
    const int*   event_type_ids = (const int*)  d_in[0];
    const int*   src_ids        = (const int*)  d_in[1];
    const float* src_mask       = (const float*)d_in[2];
    const int*   dst_ids        = (const int*)  d_in[3];
    const float* dst_mask       = (const float*)d_in[4];
    const int*   event_edge_ids = (const int*)  d_in[5];
    const float* event_emb      = (const float*)d_in[6];
    const float* event_mask     = (const float*)d_in[7];
    const float* event_ts       = (const float*)d_in[8];
    const int*   node_ids       = (const int*)  d_in[9];
    const int*   edge_ids       = (const int*)  d_in[10];
    const int*   edge_index     = (const int*)  d_in[11];
    const void*  timep          =               d_in[12];
    const float* memory         = (const float*)d_in[13];
    const float* last_update    = (const float*)d_in[14];
    const float* node_features  = (const float*)d_in[15];
    const float* edge_features  = (const float*)d_in[16];
    const float* time_w         = (const float*)d_in[17];
    const float* time_b         = (const float*)d_in[18];
    const float* gru_w_ih       = (const float*)d_in[19];
    const float* gru_w_hh       = (const float*)d_in[20];
    const float* gru_b_ih       = (const float*)d_in[21];
    const float* gru_b_hh       = (const float*)d_in[22];
    const float* wq             = (const float*)d_in[23];
    const float* bq             = (const float*)d_in[24];
    const float* wk             = (const float*)d_in[25];
    const float* bk             = (const float*)d_in[26];
    const float* wv             = (const float*)d_in[27];
    const float* bv             = (const float*)d_in[28];
    const float* we             = (const float*)d_in[29];
    const float* wskip          = (const float*)d_in[30];
    const float* bskip          = (const float*)d_in[31];
    float* out = (float*)d_out;

    float* pEc  = symf(g_Ec);
    float* pweT = symf(g_weT);

    // K1: prep (transposes, packw, flag, cnt0, zero, Hst build)
    k_prep<<<11057, 256>>>(gru_w_ih, gru_w_hh, we, wq, wk, wv, wskip,
                           bq, bk, bv, bskip, edge_ids, src_ids, dst_ids, memory);
    // K2: msg + hist + urelt
    k_phase2<<<6892, 256>>>(event_type_ids, src_ids, src_mask, dst_ids, dst_mask,
                            event_edge_ids, event_emb, event_mask, event_ts,
                            last_update, memory, time_w, time_b, edge_index, timep);
    // K3: scan
    k_scan<<<1, 512>>>();
    // K4: GRU GEMMs (z=0 gathers agg directly — no g_X round-trip)
    k_gru_gemms<<<dim3(64, 3, 2), 256>>>(gru_b_ih, gru_b_hh, src_ids, dst_ids);
    // K5: fused E-GEMM over unique eids
    k_egemm<<<(MAXE + 127) / 128, 256>>>(edge_features, time_w, time_b, pweT, pEc);
    // K6: gru_act + scatter + tag
    k_phase4<<<5378, 256>>>(edge_index, edge_ids, src_ids, dst_ids);
    // K7: q|k|v|skip GEMM with fused x gather
    k_qkvs_gemm<<<dim3((NN + 127) / 128, 4), 256>>>(node_ids, node_features, memory);
    // K8: attention (full-warp) + unflag
    k_attn<<<2500 + (NE + 255) / 256, 256>>>(out, edge_ids);
}